// round 1
// baseline (speedup 1.0000x reference)
#include <cuda_runtime.h>
#include <math.h>

// Problem constants (fixed by the dataset)
#define NN   100000
#define EE   1600000
#define ET   (EE + NN)     // edges + self loops
#define FIN  128
#define DD   64
#define HH   8
#define GG   64
#define NCLS 10
#define SLOPE 0.2f

// ---------------- scratch (device globals: allocation-free) ----------------
__device__ float g_proj[NN * DD];          // P: per-layer projection h = I @ W
__device__ float g_act [NN * DD];          // O: per-layer aggregated output / next input
__device__ float g_als [NN * HH];          // al_src per node
__device__ float g_ald [NN * HH];          // al_dst per node
__device__ float g_den [NN * HH];          // softmax denominators
__device__ float g_w   [(size_t)ET * HH];  // per-edge exp weights (54.4 MB)
__device__ float g_sums[GG * DD];          // pooled sums
__device__ float g_cnt [GG];               // node counts per graph

// ---------------- zero kernels (reference globals directly) ----------------
__global__ void zero_layer_kernel() {
    int i = blockIdx.x * blockDim.x + threadIdx.x;
    int stride = gridDim.x * blockDim.x;
    for (int k = i; k < NN * DD; k += stride) g_act[k] = 0.f;
    for (int k = i; k < NN * HH; k += stride) g_den[k] = 0.f;
}
__global__ void zero_pool_kernel() {
    int i = blockIdx.x * blockDim.x + threadIdx.x;
    if (i < GG * DD) g_sums[i] = 0.f;
    if (i < GG)      g_cnt[i]  = 0.f;
}

// ---------------- GEMM + attention-logit fusion ----------------
// h = transform(I) @ W   (W: [K, 64] row-major), and
// al_src[n,h] = sum_c h[n,h,c]*a_src[h,c]  (via 8-lane warp reduction)
// FIRST=true : layer 1, read raw I (= x), K=128
// FIRST=false: layers 2/3, read g_act with elu(v + prev_bias), K=64
template<int K, bool FIRST>
__global__ void gemm_al_kernel(const float* __restrict__ I,
                               const float* __restrict__ W,
                               const float* __restrict__ a_src,
                               const float* __restrict__ a_dst,
                               const float* __restrict__ prev_bias) {
    __shared__ float xs[4][K];
    const int x = threadIdx.x;            // 0..63 : output column
    const int y = threadIdx.y;            // 0..3  : node within block
    const int node = blockIdx.x * 4 + y;

    if (node < NN) {
        for (int kk = x; kk < K; kk += 64) {
            float v;
            if (FIRST) {
                v = I[node * K + kk];
            } else {
                v = g_act[node * K + kk] + prev_bias[kk];
                v = v > 0.f ? v : expm1f(v);      // ELU of previous layer output
            }
            xs[y][kk] = v;
        }
    }
    __syncthreads();
    if (node >= NN) return;

    float acc = 0.f;
#pragma unroll
    for (int k = 0; k < K; k++)
        acc = fmaf(xs[y][k], W[k * DD + x], acc);

    g_proj[node * DD + x] = acc;

    // attention logits: reduce over the 8 channels of each head (lanes x, x^1.. within 8-group)
    float s = acc * a_src[x];
    float d = acc * a_dst[x];
#pragma unroll
    for (int off = 4; off > 0; off >>= 1) {
        s += __shfl_xor_sync(0xffffffffu, s, off);
        d += __shfl_xor_sync(0xffffffffu, d, off);
    }
    if ((x & 7) == 0) {
        g_als[node * HH + (x >> 3)] = s;
        g_ald[node * HH + (x >> 3)] = d;
    }
}

// ---------------- edge pass A: w = exp(leakyrelu(al_src[s]+al_dst[d])), accumulate denom ----------------
// Shift-free exp is safe here: |e| is O(1) for this data distribution, and
// softmax is shift-invariant, so the result matches the max-subtracted reference.
__global__ void edge_a_kernel(const int* __restrict__ ei) {
    int i = blockIdx.x * blockDim.x + threadIdx.x;
    if (i >= ET) return;
    int src, dst;
    if (i < EE) { src = ei[i]; dst = ei[EE + i]; }
    else        { src = dst = i - EE; }          // self loop

    float4 s0 = *(const float4*)&g_als[src * HH];
    float4 s1 = *(const float4*)&g_als[src * HH + 4];
    float4 d0 = *(const float4*)&g_ald[dst * HH];
    float4 d1 = *(const float4*)&g_ald[dst * HH + 4];

    float e[HH] = { s0.x + d0.x, s0.y + d0.y, s0.z + d0.z, s0.w + d0.w,
                    s1.x + d1.x, s1.y + d1.y, s1.z + d1.z, s1.w + d1.w };
    float w[HH];
#pragma unroll
    for (int h = 0; h < HH; h++) {
        float v = e[h] > 0.f ? e[h] : SLOPE * e[h];
        w[h] = __expf(v);
    }
    float4* wp = (float4*)&g_w[(size_t)i * HH];
    wp[0] = make_float4(w[0], w[1], w[2], w[3]);
    wp[1] = make_float4(w[4], w[5], w[6], w[7]);
#pragma unroll
    for (int h = 0; h < HH; h++)
        atomicAdd(&g_den[dst * HH + h], w[h]);
}

// ---------------- edge pass B: out[dst] += h[src] * alpha  (warp per edge) ----------------
__global__ void edge_b_kernel(const int* __restrict__ ei) {
    int t = blockIdx.x * blockDim.x + threadIdx.x;
    int i = t >> 5;
    int lane = t & 31;
    if (i >= ET) return;
    int src, dst;
    if (i < EE) { src = ei[i]; dst = ei[EE + i]; }
    else        { src = dst = i - EE; }

    const size_t wbase = (size_t)i * HH;
    const int dbase = dst * HH;

    int h0 = lane >> 3;                 // heads 0..3
    float a0 = g_w[wbase + h0] / g_den[dbase + h0];
    float v0 = g_proj[src * DD + lane] * a0;
    atomicAdd(&g_act[dst * DD + lane], v0);

    int l1 = lane + 32;                 // heads 4..7
    int h1 = l1 >> 3;
    float a1 = g_w[wbase + h1] / g_den[dbase + h1];
    float v1 = g_proj[src * DD + l1] * a1;
    atomicAdd(&g_act[dst * DD + l1], v1);
}

// ---------------- pooling: sums[g] += elu(O3 + b3), counts ----------------
__global__ void pool_kernel(const int* __restrict__ batch,
                            const float* __restrict__ b3) {
    int idx = blockIdx.x * blockDim.x + threadIdx.x;
    if (idx >= NN * DD) return;
    int n = idx >> 6;
    int d = idx & 63;
    float v = g_act[idx] + b3[d];
    v = v > 0.f ? v : expm1f(v);
    int g = batch[n];
    atomicAdd(&g_sums[g * DD + d], v);
    if (d == 0) atomicAdd(&g_cnt[g], 1.0f);
}

// ---------------- final linear: out = (sums/cnt) @ lin_W + lin_b ----------------
__global__ void final_kernel(const float* __restrict__ lin_W,
                             const float* __restrict__ lin_b,
                             float* __restrict__ out) {
    int t = threadIdx.x;
    if (t >= GG * NCLS) return;
    int g = t / NCLS;
    int c = t % NCLS;
    float cnt = fmaxf(g_cnt[g], 1.0f);
    float acc = lin_b[c];
#pragma unroll
    for (int d = 0; d < DD; d++)
        acc = fmaf(g_sums[g * DD + d] / cnt, lin_W[d * NCLS + c], acc);
    out[g * NCLS + c] = acc;
}

// ---------------- launch ----------------
extern "C" void kernel_launch(void* const* d_in, const int* in_sizes, int n_in,
                              void* d_out, int out_size) {
    const float* x      = (const float*)d_in[0];
    const int*   ei     = (const int*)  d_in[1];
    const int*   batch  = (const int*)  d_in[2];
    const float* W1     = (const float*)d_in[3];
    const float* a1s    = (const float*)d_in[4];
    const float* a1d    = (const float*)d_in[5];
    const float* b1     = (const float*)d_in[6];
    const float* W2     = (const float*)d_in[7];
    const float* a2s    = (const float*)d_in[8];
    const float* a2d    = (const float*)d_in[9];
    const float* b2     = (const float*)d_in[10];
    const float* W3     = (const float*)d_in[11];
    const float* a3s    = (const float*)d_in[12];
    const float* a3d    = (const float*)d_in[13];
    const float* b3     = (const float*)d_in[14];
    const float* lin_W  = (const float*)d_in[15];
    const float* lin_b  = (const float*)d_in[16];
    float* out = (float*)d_out;

    const dim3 gblk(64, 4);
    const int ngrid  = (NN + 3) / 4;
    const int eagrid = (ET + 255) / 256;
    const int ebgrid = (int)(((long long)ET * 32 + 255) / 256);
    const int pgrid  = (NN * DD + 255) / 256;

    // ---- layer 1 ----
    gemm_al_kernel<FIN, true><<<ngrid, gblk>>>(x, W1, a1s, a1d, nullptr);
    zero_layer_kernel<<<2048, 256>>>();
    edge_a_kernel<<<eagrid, 256>>>(ei);
    edge_b_kernel<<<ebgrid, 256>>>(ei);

    // ---- layer 2 (input = elu(g_act + b1), read inside gemm before re-zeroing) ----
    gemm_al_kernel<DD, false><<<ngrid, gblk>>>(nullptr, W2, a2s, a2d, b1);
    zero_layer_kernel<<<2048, 256>>>();
    edge_a_kernel<<<eagrid, 256>>>(ei);
    edge_b_kernel<<<ebgrid, 256>>>(ei);

    // ---- layer 3 ----
    gemm_al_kernel<DD, false><<<ngrid, gblk>>>(nullptr, W3, a3s, a3d, b2);
    zero_layer_kernel<<<2048, 256>>>();
    edge_a_kernel<<<eagrid, 256>>>(ei);
    edge_b_kernel<<<ebgrid, 256>>>(ei);

    // ---- pool + classify ----
    zero_pool_kernel<<<(GG * DD + 255) / 256, 256>>>();
    pool_kernel<<<pgrid, 256>>>(batch, b3);
    final_kernel<<<1, GG * NCLS>>>(lin_W, lin_b, out);
}

// round 2
// speedup vs baseline: 1.8404x; 1.8404x over previous
#include <cuda_runtime.h>
#include <math.h>

// Problem constants (fixed by the dataset)
#define NN   100000
#define EE   1600000
#define ET   (EE + NN)     // edges + self loops
#define FIN  128
#define DD   64
#define HH   8
#define GG   64
#define NCLS 10
#define SLOPE 0.2f

// ---------------- scratch (device globals: allocation-free) ----------------
__device__ float g_proj[NN * DD];          // per-layer projection h = I @ W
__device__ float g_act [NN * DD];          // UNNORMALIZED aggregated output
__device__ float g_als [NN * HH];          // al_src per node
__device__ float g_ald [NN * HH];          // al_dst per node
__device__ float g_den [NN * HH];          // softmax denominators
__device__ float g_sums[GG * DD];          // pooled sums
__device__ float g_cnt [GG];               // node counts per graph

// ---------------- zero kernels ----------------
__global__ void zero_layer_kernel() {
    int i = blockIdx.x * blockDim.x + threadIdx.x;
    int stride = gridDim.x * blockDim.x;
    for (int k = i; k < NN * DD; k += stride) g_act[k] = 0.f;
    for (int k = i; k < NN * HH; k += stride) g_den[k] = 0.f;
}
__global__ void zero_pool_kernel() {
    int i = blockIdx.x * blockDim.x + threadIdx.x;
    if (i < GG * DD) g_sums[i] = 0.f;
    if (i < GG)      g_cnt[i]  = 0.f;
}

// ---------------- GEMM + attention-logit fusion ----------------
// h = transform(I) @ W   (W: [K, 64] row-major), and
// al_src[n,h] = sum_c h[n,h,c]*a_src[h,c]  (8-lane shuffle reduction)
// FIRST=true : layer 1, raw input x, K=128
// FIRST=false: layers 2/3: input = elu(g_act/g_den + prev_bias)  (normalization
//              of the previous layer's softmax is folded in here)
template<int K, bool FIRST>
__global__ void gemm_al_kernel(const float* __restrict__ I,
                               const float* __restrict__ W,
                               const float* __restrict__ a_src,
                               const float* __restrict__ a_dst,
                               const float* __restrict__ prev_bias) {
    __shared__ float xs[4][K];
    const int x = threadIdx.x;            // 0..63 : output column
    const int y = threadIdx.y;            // 0..3  : node within block
    const int node = blockIdx.x * 4 + y;

    if (node < NN) {
        for (int kk = x; kk < K; kk += 64) {
            float v;
            if (FIRST) {
                v = I[node * K + kk];
            } else {
                float den = g_den[node * HH + (kk >> 3)];
                v = g_act[node * K + kk] / den + prev_bias[kk];
                v = v > 0.f ? v : expm1f(v);      // ELU
            }
            xs[y][kk] = v;
        }
    }
    __syncthreads();
    if (node >= NN) return;

    float acc = 0.f;
#pragma unroll
    for (int k = 0; k < K; k++)
        acc = fmaf(xs[y][k], W[k * DD + x], acc);

    g_proj[node * DD + x] = acc;

    float s = acc * a_src[x];
    float d = acc * a_dst[x];
#pragma unroll
    for (int off = 4; off > 0; off >>= 1) {
        s += __shfl_xor_sync(0xffffffffu, s, off);
        d += __shfl_xor_sync(0xffffffffu, d, off);
    }
    if ((x & 7) == 0) {
        g_als[node * HH + (x >> 3)] = s;
        g_ald[node * HH + (x >> 3)] = d;
    }
}

// ---------------- fused edge pass ----------------
// One pass: w = exp(leakyrelu(als[src]+ald[dst])) computed inline;
// atomically accumulates den[dst] and unnormalized act[dst] += proj[src]*w.
// Warp per edge, 2 edges per warp for MLP. Shift-free exp is safe (|e|=O(1),
// softmax shift-invariant).
__global__ void edge_fused_kernel(const int* __restrict__ ei) {
    const int warp = blockIdx.x * (blockDim.x >> 5) + (threadIdx.x >> 5);
    const int lane = threadIdx.x & 31;
    const int base = warp * 2;
    if (base >= ET) return;

    int s[2], d[2];
#pragma unroll
    for (int k = 0; k < 2; k++) {
        int i = base + k;
        if (i < ET) {
            if (i < EE) { s[k] = ei[i]; d[k] = ei[EE + i]; }
            else        { s[k] = d[k] = i - EE; }          // self loop
        } else { s[k] = -1; d[k] = -1; }
    }

    // lanes 0..7 compute the 8 heads' exp-weights for both edges
    float w[2];
#pragma unroll
    for (int k = 0; k < 2; k++) {
        float wv = 0.f;
        if (s[k] >= 0 && lane < HH) {
            float e = g_als[s[k] * HH + lane] + g_ald[d[k] * HH + lane];
            e = e > 0.f ? e : SLOPE * e;
            wv = __expf(e);
            atomicAdd(&g_den[d[k] * HH + lane], wv);
        }
        w[k] = wv;
    }

    // broadcast head weights, gather proj rows, scatter-accumulate
#pragma unroll
    for (int k = 0; k < 2; k++) {
        float w0 = __shfl_sync(0xffffffffu, w[k], lane >> 3);        // heads 0..3
        float w1 = __shfl_sync(0xffffffffu, w[k], (lane >> 3) + 4);  // heads 4..7
        if (s[k] < 0) continue;
        float v0 = g_proj[s[k] * DD + lane]      * w0;
        float v1 = g_proj[s[k] * DD + lane + 32] * w1;
        atomicAdd(&g_act[d[k] * DD + lane],      v0);
        atomicAdd(&g_act[d[k] * DD + lane + 32], v1);
    }
}

// ---------------- pooling: sums[g] += elu(act/den + b3), counts ----------------
__global__ void pool_kernel(const int* __restrict__ batch,
                            const float* __restrict__ b3) {
    int idx = blockIdx.x * blockDim.x + threadIdx.x;
    if (idx >= NN * DD) return;
    int n = idx >> 6;
    int d = idx & 63;
    float den = g_den[n * HH + (d >> 3)];
    float v = g_act[idx] / den + b3[d];
    v = v > 0.f ? v : expm1f(v);
    int g = batch[n];
    atomicAdd(&g_sums[g * DD + d], v);
    if (d == 0) atomicAdd(&g_cnt[g], 1.0f);
}

// ---------------- final linear ----------------
__global__ void final_kernel(const float* __restrict__ lin_W,
                             const float* __restrict__ lin_b,
                             float* __restrict__ out) {
    int t = threadIdx.x;
    if (t >= GG * NCLS) return;
    int g = t / NCLS;
    int c = t % NCLS;
    float cnt = fmaxf(g_cnt[g], 1.0f);
    float acc = lin_b[c];
#pragma unroll
    for (int d = 0; d < DD; d++)
        acc = fmaf(g_sums[g * DD + d] / cnt, lin_W[d * NCLS + c], acc);
    out[g * NCLS + c] = acc;
}

// ---------------- launch ----------------
extern "C" void kernel_launch(void* const* d_in, const int* in_sizes, int n_in,
                              void* d_out, int out_size) {
    const float* x      = (const float*)d_in[0];
    const int*   ei     = (const int*)  d_in[1];
    const int*   batch  = (const int*)  d_in[2];
    const float* W1     = (const float*)d_in[3];
    const float* a1s    = (const float*)d_in[4];
    const float* a1d    = (const float*)d_in[5];
    const float* b1     = (const float*)d_in[6];
    const float* W2     = (const float*)d_in[7];
    const float* a2s    = (const float*)d_in[8];
    const float* a2d    = (const float*)d_in[9];
    const float* b2     = (const float*)d_in[10];
    const float* W3     = (const float*)d_in[11];
    const float* a3s    = (const float*)d_in[12];
    const float* a3d    = (const float*)d_in[13];
    const float* b3     = (const float*)d_in[14];
    const float* lin_W  = (const float*)d_in[15];
    const float* lin_b  = (const float*)d_in[16];
    float* out = (float*)d_out;

    const dim3 gblk(64, 4);
    const int ngrid  = (NN + 3) / 4;
    // fused edge kernel: 8 warps/block, 2 edges/warp -> 16 edges per block
    const int egrid  = (ET + 15) / 16;
    const int pgrid  = (NN * DD + 255) / 256;

    // ---- layer 1 ----
    gemm_al_kernel<FIN, true><<<ngrid, gblk>>>(x, W1, a1s, a1d, nullptr);
    zero_layer_kernel<<<2048, 256>>>();
    edge_fused_kernel<<<egrid, 256>>>(ei);

    // ---- layer 2 (input = elu(act/den + b1), read inside gemm before re-zero) ----
    gemm_al_kernel<DD, false><<<ngrid, gblk>>>(nullptr, W2, a2s, a2d, b1);
    zero_layer_kernel<<<2048, 256>>>();
    edge_fused_kernel<<<egrid, 256>>>(ei);

    // ---- layer 3 ----
    gemm_al_kernel<DD, false><<<ngrid, gblk>>>(nullptr, W3, a3s, a3d, b2);
    zero_layer_kernel<<<2048, 256>>>();
    edge_fused_kernel<<<egrid, 256>>>(ei);

    // ---- pool + classify ----
    zero_pool_kernel<<<(GG * DD + 255) / 256, 256>>>();
    pool_kernel<<<pgrid, 256>>>(batch, b3);
    final_kernel<<<1, GG * NCLS>>>(lin_W, lin_b, out);
}

// round 4
// speedup vs baseline: 3.3185x; 1.8031x over previous
#include <cuda_runtime.h>
#include <math.h>

#define NN   100000
#define EE   1600000
#define ET   (EE + NN)     // edges + self loops
#define FIN  128
#define DD   64
#define HH   8
#define GG   64
#define NCLS 10
#define SLOPE 0.2f

#define NB_SCAN 98         // ceil(NN/1024)

// ---------------- scratch (device globals) ----------------
__device__ float g_proj[NN * DD];        // h = I @ W
__device__ float g_act [NN * DD];        // normalized layer output
__device__ float g_als [NN * HH];
__device__ float g_ald [NN * HH];
__device__ int   g_rowptr[NN + 1];
__device__ int   g_col [ET];
__device__ int   g_cnti[NN];
__device__ int   g_fill[NN];
__device__ int   g_bsum[NB_SCAN];
__device__ int   g_boff[NB_SCAN];
__device__ float g_sums[GG * DD];
__device__ float g_cnt [GG];

// ---------------- zero aux ----------------
__global__ void zero_aux_kernel() {
    int i = blockIdx.x * blockDim.x + threadIdx.x;
    if (i < NN) { g_cnti[i] = 0; g_fill[i] = 0; }
    if (i < GG * DD) g_sums[i] = 0.f;
    if (i < GG)      g_cnt[i]  = 0.f;
}

// ---------------- CSR build ----------------
__global__ void hist_kernel(const int* __restrict__ ei) {
    int i = blockIdx.x * blockDim.x + threadIdx.x;
    if (i >= ET) return;
    int dst = (i < EE) ? ei[EE + i] : (i - EE);
    atomicAdd(&g_cnti[dst], 1);
}

// block scans 1024 items (256 threads x 4): partial exclusive scan + block sum
__global__ void scan1_kernel() {
    __shared__ int sd[256];
    const int t = threadIdx.x;
    const int base = blockIdx.x * 1024 + t * 4;
    int v[4];
#pragma unroll
    for (int i = 0; i < 4; i++) {
        int idx = base + i;
        v[i] = (idx < NN) ? g_cnti[idx] : 0;
    }
    int pre[4];
    pre[0] = 0; pre[1] = v[0]; pre[2] = v[0] + v[1]; pre[3] = v[0] + v[1] + v[2];
    int sum = pre[3] + v[3];
    sd[t] = sum;
    __syncthreads();
    for (int off = 1; off < 256; off <<= 1) {
        int x = 0;
        if (t >= off) x = sd[t - off];
        __syncthreads();
        if (t >= off) sd[t] += x;
        __syncthreads();
    }
    int toff = sd[t] - sum;   // exclusive prefix of this thread's chunk
#pragma unroll
    for (int i = 0; i < 4; i++) {
        int idx = base + i;
        if (idx < NN) g_rowptr[idx] = toff + pre[i];
    }
    if (t == 255) g_bsum[blockIdx.x] = sd[255];
}

__global__ void scan2_kernel() {
    __shared__ int sd[128];
    const int t = threadIdx.x;
    int v = (t < NB_SCAN) ? g_bsum[t] : 0;
    sd[t] = v;
    __syncthreads();
    for (int off = 1; off < 128; off <<= 1) {
        int x = 0;
        if (t >= off) x = sd[t - off];
        __syncthreads();
        if (t >= off) sd[t] += x;
        __syncthreads();
    }
    if (t < NB_SCAN) g_boff[t] = sd[t] - v;      // exclusive
    if (t == NB_SCAN - 1) g_rowptr[NN] = sd[t];  // total = ET
}

__global__ void scan3_kernel() {
    int i = blockIdx.x * blockDim.x + threadIdx.x;
    if (i < NN) g_rowptr[i] += g_boff[i >> 10];
}

__global__ void scatter_kernel(const int* __restrict__ ei) {
    int i = blockIdx.x * blockDim.x + threadIdx.x;
    if (i >= ET) return;
    int src, dst;
    if (i < EE) { src = ei[i]; dst = ei[EE + i]; }
    else        { src = dst = i - EE; }
    int pos = g_rowptr[dst] + atomicAdd(&g_fill[dst], 1);
    g_col[pos] = src;
}

// ---------------- register-tiled GEMM + attention logits ----------------
// Block: 256 threads, tile 32 nodes x 64 cols, K in chunks of 64.
// Thread (tx,ty): 2 nodes x 4 cols register tile.
// FIRST: read raw I (=x). Otherwise read g_act DIRECTLY (device symbol) with
// elu(v + prev_bias); g_act is already softmax-normalized.
template<int K, bool FIRST>
__global__ void gemm_al_kernel(const float* __restrict__ I,
                               const float* __restrict__ W,
                               const float* __restrict__ a_src,
                               const float* __restrict__ a_dst,
                               const float* __restrict__ prev_bias) {
    __shared__ float xs[32][68];    // padded rows: conflict-free
    __shared__ float Wsm[64][64];
    const int t  = threadIdx.x;
    const int tx = t & 15;
    const int ty = t >> 4;
    const int node0 = blockIdx.x * 32;   // NN % 32 == 0

    float acc[2][4] = {{0.f,0.f,0.f,0.f},{0.f,0.f,0.f,0.f}};
    const int n0 = 2 * ty, n1 = 2 * ty + 1;

    for (int kc = 0; kc < K; kc += 64) {
        // stage xs: 32 nodes x 64 k-values (512 float4, 2 per thread)
#pragma unroll
        for (int it = 0; it < 2; it++) {
            int fid  = t + it * 256;
            int node = fid >> 4;
            int kq   = (fid & 15) * 4;
            float4 v;
            if (FIRST) {
                v = *(const float4*)&I[(size_t)(node0 + node) * K + kc + kq];
            } else {
                v = *(const float4*)&g_act[(size_t)(node0 + node) * K + kc + kq];
                v.x += prev_bias[kc + kq    ];
                v.y += prev_bias[kc + kq + 1];
                v.z += prev_bias[kc + kq + 2];
                v.w += prev_bias[kc + kq + 3];
                v.x = v.x > 0.f ? v.x : expm1f(v.x);
                v.y = v.y > 0.f ? v.y : expm1f(v.y);
                v.z = v.z > 0.f ? v.z : expm1f(v.z);
                v.w = v.w > 0.f ? v.w : expm1f(v.w);
            }
            *(float4*)&xs[node][kq] = v;
        }
        // stage W chunk: 64 x 64 (1024 float4, 4 per thread)
#pragma unroll
        for (int it = 0; it < 4; it++) {
            int fid = t + it * 256;
            int kk  = fid >> 4;
            int cq  = (fid & 15) * 4;
            *(float4*)&Wsm[kk][cq] = *(const float4*)&W[(size_t)(kc + kk) * DD + cq];
        }
        __syncthreads();
#pragma unroll
        for (int k = 0; k < 64; k++) {
            float xv0 = xs[n0][k];
            float xv1 = xs[n1][k];
            float4 wv = *(const float4*)&Wsm[k][tx * 4];
            acc[0][0] = fmaf(xv0, wv.x, acc[0][0]);
            acc[0][1] = fmaf(xv0, wv.y, acc[0][1]);
            acc[0][2] = fmaf(xv0, wv.z, acc[0][2]);
            acc[0][3] = fmaf(xv0, wv.w, acc[0][3]);
            acc[1][0] = fmaf(xv1, wv.x, acc[1][0]);
            acc[1][1] = fmaf(xv1, wv.y, acc[1][1]);
            acc[1][2] = fmaf(xv1, wv.z, acc[1][2]);
            acc[1][3] = fmaf(xv1, wv.w, acc[1][3]);
        }
        __syncthreads();
    }

    const int gn0 = node0 + n0, gn1 = node0 + n1;
    *(float4*)&g_proj[(size_t)gn0 * DD + tx * 4] =
        make_float4(acc[0][0], acc[0][1], acc[0][2], acc[0][3]);
    *(float4*)&g_proj[(size_t)gn1 * DD + tx * 4] =
        make_float4(acc[1][0], acc[1][1], acc[1][2], acc[1][3]);

    // attention logits: head h = cols 8h..8h+7 -> threads tx=2h,2h+1; xor-1 pair
    float s0 = 0.f, d0 = 0.f, s1 = 0.f, d1 = 0.f;
#pragma unroll
    for (int j = 0; j < 4; j++) {
        int c = tx * 4 + j;
        float asv = a_src[c], adv = a_dst[c];
        s0 = fmaf(acc[0][j], asv, s0);
        d0 = fmaf(acc[0][j], adv, d0);
        s1 = fmaf(acc[1][j], asv, s1);
        d1 = fmaf(acc[1][j], adv, d1);
    }
    s0 += __shfl_xor_sync(0xffffffffu, s0, 1);
    d0 += __shfl_xor_sync(0xffffffffu, d0, 1);
    s1 += __shfl_xor_sync(0xffffffffu, s1, 1);
    d1 += __shfl_xor_sync(0xffffffffu, d1, 1);
    if ((tx & 1) == 0) {
        int h = tx >> 1;
        g_als[gn0 * HH + h] = s0;
        g_ald[gn0 * HH + h] = d0;
        g_als[gn1 * HH + h] = s1;
        g_ald[gn1 * HH + h] = d1;
    }
}

// ---------------- CSR edge kernel: warp per dst, no atomics ----------------
#define EW 8   // warps per block
__global__ void edge_csr_kernel() {
    __shared__ int   ss[EW][32];
    __shared__ float ws[EW][32][9];   // stride 9: conflict-free
    const int wl   = threadIdx.x >> 5;
    const int lane = threadIdx.x & 31;
    const int n = blockIdx.x * EW + wl;
    if (n >= NN) return;
    const int rs = g_rowptr[n], re = g_rowptr[n + 1];

    const float4 ad0 = *(const float4*)&g_ald[n * HH];
    const float4 ad1 = *(const float4*)&g_ald[n * HH + 4];

    float2 acc = make_float2(0.f, 0.f);
    float dn = 0.f;
    const int h = lane >> 2;          // head of cols 2*lane, 2*lane+1

    for (int base = rs; base < re; base += 32) {
        const int e = base + lane;
        if (e < re) {
            int src = g_col[e];
            ss[wl][lane] = src;
            float4 s0 = *(const float4*)&g_als[src * HH];
            float4 s1 = *(const float4*)&g_als[src * HH + 4];
            float ev[8] = { s0.x + ad0.x, s0.y + ad0.y, s0.z + ad0.z, s0.w + ad0.w,
                            s1.x + ad1.x, s1.y + ad1.y, s1.z + ad1.z, s1.w + ad1.w };
#pragma unroll
            for (int hh = 0; hh < 8; hh++) {
                float v = ev[hh] > 0.f ? ev[hh] : SLOPE * ev[hh];
                ws[wl][lane][hh] = __expf(v);
            }
        }
        __syncwarp();
        const int cnt = min(32, re - base);
#pragma unroll 4
        for (int j = 0; j < cnt; j++) {
            int   sj = ss[wl][j];
            float wj = ws[wl][j][h];
            dn += wj;
            float2 p = *(const float2*)&g_proj[(size_t)sj * DD + 2 * lane];
            acc.x = fmaf(p.x, wj, acc.x);
            acc.y = fmaf(p.y, wj, acc.y);
        }
        __syncwarp();
    }
    const float inv = 1.f / dn;       // softmax normalization folded here
    *(float2*)&g_act[(size_t)n * DD + 2 * lane] = make_float2(acc.x * inv, acc.y * inv);
}

// ---------------- pooling ----------------
__global__ void pool_kernel(const int* __restrict__ batch,
                            const float* __restrict__ b3) {
    int idx = blockIdx.x * blockDim.x + threadIdx.x;
    if (idx >= NN * DD) return;
    int n = idx >> 6;
    int d = idx & 63;
    float v = g_act[idx] + b3[d];
    v = v > 0.f ? v : expm1f(v);
    int g = batch[n];
    atomicAdd(&g_sums[g * DD + d], v);
    if (d == 0) atomicAdd(&g_cnt[g], 1.0f);
}

// ---------------- final linear ----------------
__global__ void final_kernel(const float* __restrict__ lin_W,
                             const float* __restrict__ lin_b,
                             float* __restrict__ out) {
    int t = threadIdx.x;
    if (t >= GG * NCLS) return;
    int g = t / NCLS;
    int c = t % NCLS;
    float cnt = fmaxf(g_cnt[g], 1.0f);
    float acc = lin_b[c];
#pragma unroll
    for (int d = 0; d < DD; d++)
        acc = fmaf(g_sums[g * DD + d] / cnt, lin_W[d * NCLS + c], acc);
    out[g * NCLS + c] = acc;
}

// ---------------- launch ----------------
extern "C" void kernel_launch(void* const* d_in, const int* in_sizes, int n_in,
                              void* d_out, int out_size) {
    const float* x      = (const float*)d_in[0];
    const int*   ei     = (const int*)  d_in[1];
    const int*   batch  = (const int*)  d_in[2];
    const float* W1     = (const float*)d_in[3];
    const float* a1s    = (const float*)d_in[4];
    const float* a1d    = (const float*)d_in[5];
    const float* b1     = (const float*)d_in[6];
    const float* W2     = (const float*)d_in[7];
    const float* a2s    = (const float*)d_in[8];
    const float* a2d    = (const float*)d_in[9];
    const float* b2     = (const float*)d_in[10];
    const float* W3     = (const float*)d_in[11];
    const float* a3s    = (const float*)d_in[12];
    const float* a3d    = (const float*)d_in[13];
    const float* b3     = (const float*)d_in[14];
    const float* lin_W  = (const float*)d_in[15];
    const float* lin_b  = (const float*)d_in[16];
    float* out = (float*)d_out;

    const int ngrid = NN / 32;                 // 3125
    const int egrid = (NN + EW - 1) / EW;      // 12500
    const int etg   = (ET + 255) / 256;
    const int pgrid = (NN * DD) / 256;

    // ---- CSR build (per launch; graph-capturable) ----
    zero_aux_kernel<<<(NN + 255) / 256, 256>>>();
    hist_kernel<<<etg, 256>>>(ei);
    scan1_kernel<<<NB_SCAN, 256>>>();
    scan2_kernel<<<1, 128>>>();
    scan3_kernel<<<(NN + 255) / 256, 256>>>();
    scatter_kernel<<<etg, 256>>>(ei);

    // ---- layer 1 ----
    gemm_al_kernel<FIN, true><<<ngrid, 256>>>(x, W1, a1s, a1d, nullptr);
    edge_csr_kernel<<<egrid, 256>>>();

    // ---- layer 2 (reads g_act internally) ----
    gemm_al_kernel<DD, false><<<ngrid, 256>>>(nullptr, W2, a2s, a2d, b1);
    edge_csr_kernel<<<egrid, 256>>>();

    // ---- layer 3 ----
    gemm_al_kernel<DD, false><<<ngrid, 256>>>(nullptr, W3, a3s, a3d, b2);
    edge_csr_kernel<<<egrid, 256>>>();

    // ---- pool + classify ----
    pool_kernel<<<pgrid, 256>>>(batch, b3);
    final_kernel<<<1, GG * NCLS>>>(lin_W, lin_b, out);
}